// round 4
// baseline (speedup 1.0000x reference)
#include <cuda_runtime.h>

// iPUNet forward, fully fused. One CTA (128 threads) per point, BN=2048 CTAs.
// Single-wave, issue-count-optimized:
//  - distance phase: float4 loads, 8 pts/thread, byte-packed mask (no ballots)
//  - feat_off: 2-step partial shuffle reduce + 8-lane smem atomics
//  - output: precomputed per-cell index bitmask (no 16-way search)
//
// Shapes: B=2, N=1024, FEAT=128, NSAMPLE=48, GRID=7, RADIUS=0.3
// Output (f32, 417792 elems):
//   oris [0,6144) | nors [6144,12288) | pts_ups [12288,110592)
//   pts_offset [110592,116736) | pts_up [116736,417792)

#define NPTS   1024
#define FEATD  128
#define NS     48

#define OFF_ORIS   0
#define OFF_NORS   6144
#define OFF_UPS    12288
#define OFF_OFFSET 110592
#define OFF_PTSUP  116736

__device__ __forceinline__ float wredf(float x) {
#pragma unroll
    for (int o = 16; o; o >>= 1) x += __shfl_xor_sync(0xffffffffu, x, o);
    return x;
}

__global__ __launch_bounds__(128, 14)
void ipunet_kernel(const float* __restrict__ xyz,
                   const float* __restrict__ feat,
                   const float* __restrict__ W0, const float* __restrict__ b0,
                   const float* __restrict__ W1, const float* __restrict__ b1,
                   const float* __restrict__ Wu, const int* __restrict__ g_index,
                   float* __restrict__ out)
{
    const int p    = blockIdx.x;       // global point id 0..2047
    const int b    = p >> 10;
    const int pid  = p & 1023;
    const int t    = threadIdx.x;      // 0..127
    const int lane = t & 31;
    const int warp = t >> 5;           // 0..3

    __shared__ float    s_rot[9];
    __shared__ float    s_part[4][6];
    __shared__ unsigned s_mask[32];     // 1024-bit mask, byte t = points 8t..8t+7
    __shared__ int      s_nbr[NS];
    __shared__ int      s_win[91];
    __shared__ int      s_cnt;
    __shared__ int      s_nwin;
    __shared__ int      s_wlist[NS];    // packed (cell<<10)|nbr
    __shared__ float    s_off[49 * 3];
    __shared__ unsigned s_upmask[49];   // bit q set iff index[q]==cell s

    // ---- center ------------------------------------------------------------
    const float* xb = xyz + b * 3 * NPTS;
    const float cx = __ldg(&xb[pid]);
    const float cy = __ldg(&xb[NPTS + pid]);
    const float cz = __ldg(&xb[2 * NPTS + pid]);
    const float c2 = cx * cx + cy * cy + cz * cz;

    // ---- smem init -----------------------------------------------------------
    if (t < 91) s_win[t] = -1;
    if (t == 0) s_nwin = 0;
    if (t < 49) s_upmask[t] = 0u;
    s_off[t] = 0.0f;
    if (t < 19) s_off[128 + t] = 0.0f;

    // ---- merged: ball query (8 pts/thread, vectorized) + oris/nors matvec ----
    {
        float f   = __ldg(&feat[(p << 7) + t]);
        float w0a = __ldg(&W0[t]), w0b = __ldg(&W0[128 + t]), w0c = __ldg(&W0[256 + t]);
        float w1a = __ldg(&W1[t]), w1b = __ldg(&W1[128 + t]), w1c = __ldg(&W1[256 + t]);

        const float4* x4 = (const float4*)xb;
        const float4* y4 = (const float4*)(xb + NPTS);
        const float4* z4 = (const float4*)(xb + 2 * NPTS);
        float4 xa = __ldg(&x4[2 * t]), xbv = __ldg(&x4[2 * t + 1]);
        float4 ya = __ldg(&y4[2 * t]), ybv = __ldg(&y4[2 * t + 1]);
        float4 za = __ldg(&z4[2 * t]), zbv = __ldg(&z4[2 * t + 1]);

        unsigned byte = 0;
        {
            const float* px = &xa.x; const float* py = &ya.x; const float* pz = &za.x;
#pragma unroll
            for (int q = 0; q < 4; q++) {
                float X = px[q], Y = py[q], Z = pz[q];
                float d = -2.0f * (cx * X + cy * Y + cz * Z) + c2 + (X * X + Y * Y + Z * Z);
                byte |= (d > 0.09f ? 0u : 1u) << q;
            }
            const float* qx = &xbv.x; const float* qy = &ybv.x; const float* qz = &zbv.x;
#pragma unroll
            for (int q = 0; q < 4; q++) {
                float X = qx[q], Y = qy[q], Z = qz[q];
                float d = -2.0f * (cx * X + cy * Y + cz * Z) + c2 + (X * X + Y * Y + Z * Z);
                byte |= (d > 0.09f ? 0u : 1u) << (4 + q);
            }
        }
        ((unsigned char*)s_mask)[t] = (unsigned char)byte;

        float q0 = wredf(f * w0a), q1 = wredf(f * w0b), q2 = wredf(f * w0c);
        float q3 = wredf(f * w1a), q4 = wredf(f * w1b), q5 = wredf(f * w1c);
        if (lane == 0) {
            s_part[warp][0] = q0; s_part[warp][1] = q1; s_part[warp][2] = q2;
            s_part[warp][3] = q3; s_part[warp][4] = q4; s_part[warp][5] = q5;
        }
    }
    __syncthreads();

    // ---- concurrent: rotation (t==32) | extraction (warp 0) | upmask (warp 2)
    if (t >= 64 && t < 80)
        atomicOr(&s_upmask[__ldg(&g_index[t - 64])], 1u << (t - 64));

    if (t == 32) {
        float ov[3], nv[3];
#pragma unroll
        for (int d = 0; d < 3; d++) {
            ov[d] = s_part[0][d]   + s_part[1][d]   + s_part[2][d]   + s_part[3][d]   + __ldg(&b0[d]);
            nv[d] = s_part[0][3+d] + s_part[1][3+d] + s_part[2][3+d] + s_part[3][3+d] + __ldg(&b1[d]);
        }
        float io = 1.0f / (sqrtf(ov[0]*ov[0]+ov[1]*ov[1]+ov[2]*ov[2] + 1e-8f) + 1e-10f);
        ov[0] *= io; ov[1] *= io; ov[2] *= io;
        float in = 1.0f / (sqrtf(nv[0]*nv[0]+nv[1]*nv[1]+nv[2]*nv[2] + 1e-8f) + 1e-10f);
        nv[0] *= in; nv[1] *= in; nv[2] *= in;

        float r90[3];
        r90[0] = ov[1]*nv[2] - ov[2]*nv[1];
        r90[1] = ov[2]*nv[0] - ov[0]*nv[2];
        r90[2] = ov[0]*nv[1] - ov[1]*nv[0];
        float ir = 1.0f / (sqrtf(r90[0]*r90[0]+r90[1]*r90[1]+r90[2]*r90[2] + 1e-8f) + 1e-10f);
        r90[0] *= ir; r90[1] *= ir; r90[2] *= ir;

        float o0[3];
        o0[0] = r90[1]*nv[2] - r90[2]*nv[1];
        o0[1] = r90[2]*nv[0] - r90[0]*nv[2];
        o0[2] = r90[0]*nv[1] - r90[1]*nv[0];
        float i0 = 1.0f / (sqrtf(o0[0]*o0[0]+o0[1]*o0[1]+o0[2]*o0[2] + 1e-8f) + 1e-10f);
        o0[0] *= i0; o0[1] *= i0; o0[2] *= i0;

        s_rot[0] = o0[0];  s_rot[1] = o0[1];  s_rot[2] = o0[2];
        s_rot[3] = r90[0]; s_rot[4] = r90[1]; s_rot[5] = r90[2];
        s_rot[6] = nv[0];  s_rot[7] = nv[1];  s_rot[8] = nv[2];

#pragma unroll
        for (int d = 0; d < 3; d++) {
            out[OFF_ORIS + p * 3 + d] = ov[d];
            out[OFF_NORS + p * 3 + d] = nv[d];
        }
    }
    if (warp == 0) {
        unsigned m = s_mask[lane];
        int pc = __popc(m);
        int incl = pc;
#pragma unroll
        for (int o = 1; o < 32; o <<= 1) {
            int v = __shfl_up_sync(0xffffffffu, incl, o);
            if (lane >= o) incl += v;
        }
        int excl = incl - pc;
        if (lane == 31) s_cnt = (incl < NS) ? incl : NS;
        unsigned mm = m;
        int r = excl;
        while (mm && r < NS) {
            int bpos = __ffs(mm) - 1;
            s_nbr[r] = (lane << 5) + bpos;
            mm &= mm - 1;
            r++;
        }
    }
    __syncthreads();

    // ---- local coords -> cell; last-wins winner; compact --------------------
    int myCell = -1, myJ = 0;
    if (t < NS) {
        myJ = (t < s_cnt) ? s_nbr[t] : s_nbr[0];
        float lx = __ldg(&xb[myJ]) - cx;
        float ly = __ldg(&xb[NPTS + myJ]) - cy;
        float lz = __ldg(&xb[2 * NPTS + myJ]) - cz;
        int c[3];
#pragma unroll
        for (int d = 0; d < 3; d++) {
            float lp = lx * s_rot[d*3+0] + ly * s_rot[d*3+1] + lz * s_rot[d*3+2];
            float v = rintf((lp + 0.3f) / 0.6f * 6.0f);
            int ci = (int)v;
            ci = ci < 0 ? 0 : (ci > 6 ? 6 : ci);
            c[d] = ci;
        }
        myCell = c[0] * 7 + c[1] * 7 + c[2];   // reference quirk: both *g
        atomicMax(&s_win[myCell], t);
    }
    __syncthreads();
    if (t < NS && s_win[myCell] == t) {
        int w = atomicAdd(&s_nwin, 1);
        s_wlist[w] = (myCell << 10) | myJ;
    }
    __syncthreads();

    // ---- sparse feat_off: compacted winners, prefetch, partial reduce -------
    {
        const int nw = s_nwin;
        const float4* fb = (const float4*)(feat + ((long)b << 17));
        int i = warp;
        float4 v = make_float4(0.f, 0.f, 0.f, 0.f);
        int cell = 0;
        if (i < nw) {
            int pk = s_wlist[i];
            cell = pk >> 10;
            v = __ldg(&fb[((pk & 1023) << 5) + lane]);
        }
        while (i < nw) {
            int inext = i + 4;
            float4 vn = v; int celln = cell;
            if (inext < nw) {
                int pk = s_wlist[inext];
                celln = pk >> 10;
                vn = __ldg(&fb[((pk & 1023) << 5) + lane]);
            }
            int k  = cell % 7;
            int p5 = (cell / 49) * 7 + (cell / 7) % 7;
            const float* wb = Wu + lane * 84 + k * 3;   // lane*4 channels * 21
            float a0 = v.x * __ldg(wb+0)  + v.y * __ldg(wb+21)
                     + v.z * __ldg(wb+42) + v.w * __ldg(wb+63);
            float a1 = v.x * __ldg(wb+1)  + v.y * __ldg(wb+22)
                     + v.z * __ldg(wb+43) + v.w * __ldg(wb+64);
            float a2 = v.x * __ldg(wb+2)  + v.y * __ldg(wb+23)
                     + v.z * __ldg(wb+44) + v.w * __ldg(wb+65);
            // 2-step partial reduce: groups of 4 lanes agree; lanes 0-7 hold
            // the 8 group partials.
            a0 += __shfl_xor_sync(0xffffffffu, a0, 16);
            a1 += __shfl_xor_sync(0xffffffffu, a1, 16);
            a2 += __shfl_xor_sync(0xffffffffu, a2, 16);
            a0 += __shfl_xor_sync(0xffffffffu, a0, 8);
            a1 += __shfl_xor_sync(0xffffffffu, a1, 8);
            a2 += __shfl_xor_sync(0xffffffffu, a2, 8);
            if (lane < 8) {
                atomicAdd(&s_off[p5 * 3 + 0], a0);
                atomicAdd(&s_off[p5 * 3 + 1], a1);
                atomicAdd(&s_off[p5 * 3 + 2], a2);
            }
            v = vn; cell = celln; i = inext;
        }
    }
    __syncthreads();

    // ---- up = vals + feat_off; rotate back; write outputs -------------------
    if (t < 49) {
        int s = t;
        float u0 = (float)(s / 7 - 3) * 0.1f + s_off[s * 3 + 0];
        float u1 = (float)(s % 7 - 3) * 0.1f + s_off[s * 3 + 1];
        float u2 = s_off[s * 3 + 2];
        float w[3];
#pragma unroll
        for (int d = 0; d < 3; d++)
            w[d] = u0 * s_rot[d] + u1 * s_rot[3 + d] + u2 * s_rot[6 + d]
                 + (d == 0 ? cx : (d == 1 ? cy : cz));

        float* o_up = out + OFF_PTSUP + (p * 49 + s) * 3;
        o_up[0] = w[0]; o_up[1] = w[1]; o_up[2] = w[2];

        if (s == 24) {
            float* o_of = out + OFF_OFFSET + p * 3;
            o_of[0] = w[0]; o_of[1] = w[1]; o_of[2] = w[2];
        }
        unsigned m = s_upmask[s];
        while (m) {
            int q = __ffs(m) - 1;
            m &= m - 1;
            float* o_u = out + OFF_UPS + (p * 16 + q) * 3;
            o_u[0] = w[0]; o_u[1] = w[1]; o_u[2] = w[2];
        }
    }
}

extern "C" void kernel_launch(void* const* d_in, const int* in_sizes, int n_in,
                              void* d_out, int out_size)
{
    const float* xyz   = (const float*)d_in[0];
    const float* feat  = (const float*)d_in[1];
    const float* W0    = (const float*)d_in[2];
    const float* b0    = (const float*)d_in[3];
    const float* W1    = (const float*)d_in[4];
    const float* b1    = (const float*)d_in[5];
    const float* Wu    = (const float*)d_in[6];
    const int*   index = (const int*)d_in[7];
    float* out = (float*)d_out;

    ipunet_kernel<<<2048, 128>>>(xyz, feat, W0, b0, W1, b1, Wu, index, out);
}

// round 5
// speedup vs baseline: 1.6250x; 1.6250x over previous
#include <cuda_runtime.h>

// iPUNet forward, fully fused. One CTA (128 threads) per point, BN=2048 CTAs.
// R3 base + restructured feat_off (4 winners/warp-iter, 8 lanes/winner,
// 3-step group reduce, spread-address atomics) + upmask output.
//
// Shapes: B=2, N=1024, FEAT=128, NSAMPLE=48, GRID=7, RADIUS=0.3
// Output (f32, 417792 elems):
//   oris [0,6144) | nors [6144,12288) | pts_ups [12288,110592)
//   pts_offset [110592,116736) | pts_up [116736,417792)

#define NPTS   1024
#define FEATD  128
#define NS     48

#define OFF_ORIS   0
#define OFF_NORS   6144
#define OFF_UPS    12288
#define OFF_OFFSET 110592
#define OFF_PTSUP  116736

__device__ __forceinline__ float wredf(float x) {
#pragma unroll
    for (int o = 16; o; o >>= 1) x += __shfl_xor_sync(0xffffffffu, x, o);
    return x;
}

__global__ __launch_bounds__(128)
void ipunet_kernel(const float* __restrict__ xyz,
                   const float* __restrict__ feat,
                   const float* __restrict__ W0, const float* __restrict__ b0,
                   const float* __restrict__ W1, const float* __restrict__ b1,
                   const float* __restrict__ Wu, const int* __restrict__ g_index,
                   float* __restrict__ out)
{
    const int p    = blockIdx.x;       // global point id 0..2047
    const int b    = p >> 10;
    const int pid  = p & 1023;
    const int t    = threadIdx.x;      // 0..127
    const int lane = t & 31;
    const int warp = t >> 5;           // 0..3

    __shared__ float    s_rot[9];
    __shared__ float    s_part[4][6];
    __shared__ unsigned s_mask[32];
    __shared__ int      s_nbr[NS];
    __shared__ int      s_win[91];
    __shared__ int      s_cnt;
    __shared__ int      s_nwin;
    __shared__ int      s_wlist[NS];    // packed (cell<<10)|nbr
    __shared__ float    s_off[49 * 3];
    __shared__ unsigned s_upmask[49];   // bit q set iff index[q]==s

    // ---- center --------------------------------------------------------------
    const float* xb = xyz + b * 3 * NPTS;
    const float cx = __ldg(&xb[pid]);
    const float cy = __ldg(&xb[NPTS + pid]);
    const float cz = __ldg(&xb[2 * NPTS + pid]);
    const float c2 = cx * cx + cy * cy + cz * cz;

    // ---- smem init -------------------------------------------------------------
    if (t < 91) s_win[t] = -1;
    if (t == 0) s_nwin = 0;
    if (t < 49) s_upmask[t] = 0u;
    s_off[t] = 0.0f;
    if (t < 19) s_off[128 + t] = 0.0f;

    // ---- merged: ball query (8 segs, scalar loads) + oris/nors matvec ----------
    {
        float f   = __ldg(&feat[(p << 7) + t]);
        float w0a = __ldg(&W0[t]), w0b = __ldg(&W0[128 + t]), w0c = __ldg(&W0[256 + t]);
        float w1a = __ldg(&W1[t]), w1b = __ldg(&W1[128 + t]), w1c = __ldg(&W1[256 + t]);

#pragma unroll
        for (int seg = 0; seg < 8; seg++) {
            int j = seg * 128 + t;
            float px = __ldg(&xb[j]);
            float py = __ldg(&xb[NPTS + j]);
            float pz = __ldg(&xb[2 * NPTS + j]);
            float d = -2.0f * (cx * px + cy * py + cz * pz) + c2
                      + (px * px + py * py + pz * pz);
            unsigned m = __ballot_sync(0xffffffffu, !(d > 0.09f));
            if (lane == 0) s_mask[seg * 4 + warp] = m;
        }

        float q0 = wredf(f * w0a), q1 = wredf(f * w0b), q2 = wredf(f * w0c);
        float q3 = wredf(f * w1a), q4 = wredf(f * w1b), q5 = wredf(f * w1c);
        if (lane == 0) {
            s_part[warp][0] = q0; s_part[warp][1] = q1; s_part[warp][2] = q2;
            s_part[warp][3] = q3; s_part[warp][4] = q4; s_part[warp][5] = q5;
        }
    }
    __syncthreads();

    // ---- concurrent: rotation (t==32) | extraction (warp 0) | upmask (warp 2) --
    if (t >= 64 && t < 80)
        atomicOr(&s_upmask[__ldg(&g_index[t - 64])], 1u << (t - 64));

    if (t == 32) {
        float ov[3], nv[3];
#pragma unroll
        for (int d = 0; d < 3; d++) {
            ov[d] = s_part[0][d]   + s_part[1][d]   + s_part[2][d]   + s_part[3][d]   + __ldg(&b0[d]);
            nv[d] = s_part[0][3+d] + s_part[1][3+d] + s_part[2][3+d] + s_part[3][3+d] + __ldg(&b1[d]);
        }
        float io = 1.0f / (sqrtf(ov[0]*ov[0]+ov[1]*ov[1]+ov[2]*ov[2] + 1e-8f) + 1e-10f);
        ov[0] *= io; ov[1] *= io; ov[2] *= io;
        float in = 1.0f / (sqrtf(nv[0]*nv[0]+nv[1]*nv[1]+nv[2]*nv[2] + 1e-8f) + 1e-10f);
        nv[0] *= in; nv[1] *= in; nv[2] *= in;

        float r90[3];
        r90[0] = ov[1]*nv[2] - ov[2]*nv[1];
        r90[1] = ov[2]*nv[0] - ov[0]*nv[2];
        r90[2] = ov[0]*nv[1] - ov[1]*nv[0];
        float ir = 1.0f / (sqrtf(r90[0]*r90[0]+r90[1]*r90[1]+r90[2]*r90[2] + 1e-8f) + 1e-10f);
        r90[0] *= ir; r90[1] *= ir; r90[2] *= ir;

        float o0[3];
        o0[0] = r90[1]*nv[2] - r90[2]*nv[1];
        o0[1] = r90[2]*nv[0] - r90[0]*nv[2];
        o0[2] = r90[0]*nv[1] - r90[1]*nv[0];
        float i0 = 1.0f / (sqrtf(o0[0]*o0[0]+o0[1]*o0[1]+o0[2]*o0[2] + 1e-8f) + 1e-10f);
        o0[0] *= i0; o0[1] *= i0; o0[2] *= i0;

        s_rot[0] = o0[0];  s_rot[1] = o0[1];  s_rot[2] = o0[2];
        s_rot[3] = r90[0]; s_rot[4] = r90[1]; s_rot[5] = r90[2];
        s_rot[6] = nv[0];  s_rot[7] = nv[1];  s_rot[8] = nv[2];

#pragma unroll
        for (int d = 0; d < 3; d++) {
            out[OFF_ORIS + p * 3 + d] = ov[d];
            out[OFF_NORS + p * 3 + d] = nv[d];
        }
    }
    if (warp == 0) {
        unsigned m = s_mask[lane];
        int pc = __popc(m);
        int incl = pc;
#pragma unroll
        for (int o = 1; o < 32; o <<= 1) {
            int v = __shfl_up_sync(0xffffffffu, incl, o);
            if (lane >= o) incl += v;
        }
        int excl = incl - pc;
        if (lane == 31) s_cnt = (incl < NS) ? incl : NS;
        unsigned mm = m;
        int r = excl;
        while (mm && r < NS) {
            int bpos = __ffs(mm) - 1;
            s_nbr[r] = (lane << 5) + bpos;
            mm &= mm - 1;
            r++;
        }
    }
    __syncthreads();

    // ---- local coords -> cell; last-wins winner; compact -----------------------
    int myCell = -1, myJ = 0;
    if (t < NS) {
        myJ = (t < s_cnt) ? s_nbr[t] : s_nbr[0];
        float lx = __ldg(&xb[myJ]) - cx;
        float ly = __ldg(&xb[NPTS + myJ]) - cy;
        float lz = __ldg(&xb[2 * NPTS + myJ]) - cz;
        int c[3];
#pragma unroll
        for (int d = 0; d < 3; d++) {
            float lp = lx * s_rot[d*3+0] + ly * s_rot[d*3+1] + lz * s_rot[d*3+2];
            float v = rintf((lp + 0.3f) / 0.6f * 6.0f);
            int ci = (int)v;
            ci = ci < 0 ? 0 : (ci > 6 ? 6 : ci);
            c[d] = ci;
        }
        myCell = c[0] * 7 + c[1] * 7 + c[2];   // reference quirk: both *g
        atomicMax(&s_win[myCell], t);
    }
    __syncthreads();
    if (t < NS && s_win[myCell] == t) {
        int w = atomicAdd(&s_nwin, 1);
        s_wlist[w] = (myCell << 10) | myJ;
    }
    __syncthreads();

    // ---- sparse feat_off: 4 winners per warp-iteration, 8 lanes per winner -----
    {
        const int nw = s_nwin;
        const float4* fb = (const float4*)(feat + ((long)b << 17));
        const int sub  = lane >> 3;        // which of 4 winners this lane serves
        const int lsub = lane & 7;         // channel-group within winner (16 ch)

        for (int g = warp * 4; g < nw; g += 16) {
            int i = g + sub;
            bool valid = (i < nw);
            int pk   = s_wlist[valid ? i : 0];
            int cell = pk >> 10;
            int nbr  = pk & 1023;

            // 16 channels per lane: 4 x float4
            const float4* fp = &fb[(nbr << 5) + (lsub << 2)];
            float4 v0 = __ldg(&fp[0]);
            float4 v1 = __ldg(&fp[1]);
            float4 v2 = __ldg(&fp[2]);
            float4 v3 = __ldg(&fp[3]);

            int k  = cell % 7;
            int p5 = (cell / 49) * 7 + (cell / 7) % 7;

            // weights for channels c0..c0+15, column k  (Wu layout [c][7][3])
            const float* wb = Wu + (lsub << 4) * 21 + k * 3;
            float a0, a1, a2;
            {
                float x;
                a0  = v0.x * __ldg(wb+0);    a1  = v0.x * __ldg(wb+1);    a2  = v0.x * __ldg(wb+2);
                x = v0.y; a0 += x*__ldg(wb+21);  a1 += x*__ldg(wb+22);  a2 += x*__ldg(wb+23);
                x = v0.z; a0 += x*__ldg(wb+42);  a1 += x*__ldg(wb+43);  a2 += x*__ldg(wb+44);
                x = v0.w; a0 += x*__ldg(wb+63);  a1 += x*__ldg(wb+64);  a2 += x*__ldg(wb+65);
                x = v1.x; a0 += x*__ldg(wb+84);  a1 += x*__ldg(wb+85);  a2 += x*__ldg(wb+86);
                x = v1.y; a0 += x*__ldg(wb+105); a1 += x*__ldg(wb+106); a2 += x*__ldg(wb+107);
                x = v1.z; a0 += x*__ldg(wb+126); a1 += x*__ldg(wb+127); a2 += x*__ldg(wb+128);
                x = v1.w; a0 += x*__ldg(wb+147); a1 += x*__ldg(wb+148); a2 += x*__ldg(wb+149);
                x = v2.x; a0 += x*__ldg(wb+168); a1 += x*__ldg(wb+169); a2 += x*__ldg(wb+170);
                x = v2.y; a0 += x*__ldg(wb+189); a1 += x*__ldg(wb+190); a2 += x*__ldg(wb+191);
                x = v2.z; a0 += x*__ldg(wb+210); a1 += x*__ldg(wb+211); a2 += x*__ldg(wb+212);
                x = v2.w; a0 += x*__ldg(wb+231); a1 += x*__ldg(wb+232); a2 += x*__ldg(wb+233);
                x = v3.x; a0 += x*__ldg(wb+252); a1 += x*__ldg(wb+253); a2 += x*__ldg(wb+254);
                x = v3.y; a0 += x*__ldg(wb+273); a1 += x*__ldg(wb+274); a2 += x*__ldg(wb+275);
                x = v3.z; a0 += x*__ldg(wb+294); a1 += x*__ldg(wb+295); a2 += x*__ldg(wb+296);
                x = v3.w; a0 += x*__ldg(wb+315); a1 += x*__ldg(wb+316); a2 += x*__ldg(wb+317);
            }

            // reduce within each 8-lane group
            a0 += __shfl_xor_sync(0xffffffffu, a0, 4);
            a1 += __shfl_xor_sync(0xffffffffu, a1, 4);
            a2 += __shfl_xor_sync(0xffffffffu, a2, 4);
            a0 += __shfl_xor_sync(0xffffffffu, a0, 2);
            a1 += __shfl_xor_sync(0xffffffffu, a1, 2);
            a2 += __shfl_xor_sync(0xffffffffu, a2, 2);
            a0 += __shfl_xor_sync(0xffffffffu, a0, 1);
            a1 += __shfl_xor_sync(0xffffffffu, a1, 1);
            a2 += __shfl_xor_sync(0xffffffffu, a2, 1);

            if (lsub == 0 && valid) {
                atomicAdd(&s_off[p5 * 3 + 0], a0);
                atomicAdd(&s_off[p5 * 3 + 1], a1);
                atomicAdd(&s_off[p5 * 3 + 2], a2);
            }
        }
    }
    __syncthreads();

    // ---- up = vals + feat_off; rotate back; write outputs ----------------------
    if (t < 49) {
        int s = t;
        float u0 = (float)(s / 7 - 3) * 0.1f + s_off[s * 3 + 0];
        float u1 = (float)(s % 7 - 3) * 0.1f + s_off[s * 3 + 1];
        float u2 = s_off[s * 3 + 2];
        float w[3];
#pragma unroll
        for (int d = 0; d < 3; d++)
            w[d] = u0 * s_rot[d] + u1 * s_rot[3 + d] + u2 * s_rot[6 + d]
                 + (d == 0 ? cx : (d == 1 ? cy : cz));

        float* o_up = out + OFF_PTSUP + (p * 49 + s) * 3;
        o_up[0] = w[0]; o_up[1] = w[1]; o_up[2] = w[2];

        if (s == 24) {
            float* o_of = out + OFF_OFFSET + p * 3;
            o_of[0] = w[0]; o_of[1] = w[1]; o_of[2] = w[2];
        }
        unsigned m = s_upmask[s];
        while (m) {
            int q = __ffs(m) - 1;
            m &= m - 1;
            float* o_u = out + OFF_UPS + (p * 16 + q) * 3;
            o_u[0] = w[0]; o_u[1] = w[1]; o_u[2] = w[2];
        }
    }
}

extern "C" void kernel_launch(void* const* d_in, const int* in_sizes, int n_in,
                              void* d_out, int out_size)
{
    const float* xyz   = (const float*)d_in[0];
    const float* feat  = (const float*)d_in[1];
    const float* W0    = (const float*)d_in[2];
    const float* b0    = (const float*)d_in[3];
    const float* W1    = (const float*)d_in[4];
    const float* b1    = (const float*)d_in[5];
    const float* Wu    = (const float*)d_in[6];
    const int*   index = (const int*)d_in[7];
    float* out = (float*)d_out;

    ipunet_kernel<<<2048, 128>>>(xyz, feat, W0, b0, W1, b1, Wu, index, out);
}